// round 15
// baseline (speedup 1.0000x reference)
#include <cuda_runtime.h>
#include <math.h>

#define NB   8
#define CC   256
#define HH   192
#define WW   320
#define FHH  768
#define FWW  1280
#define HWc  (HH*WW)          // 61440 coarse pixels
#define NHW  (NB*HWc)         // 491520
#define FHW  (FHH*FWW)        // 983040 fine pixels
#define FUSED_ELEMS ((size_t)NB*CC*HWc)   // 125,829,120
#define CH   16               // channels per fuse block
#define HCH  (CH/2)           // 8: loop count, two channels per iteration
#define CSTRIDE ((size_t)HCH*HWc)  // element offset between the channel pair
#define CHUNKS (CC/CH)        // 16
#define FUSE_BLOCKS  (HWc/256 * NB * CHUNKS)   // 240*128 = 30720
#define UP_BLOCKS    (NB*FHH*WW/256)           // 7680
#define ALL_BLOCKS   (FUSE_BLOCKS + UP_BLOCKS) // 38400 = 5 * 7680

// Precomputed per-(n,h,w):
//   g_w:  (b*w00, b*w01, b*w10, b*w11) — bilinear weights * rm1n/s, invalid taps zeroed
//   g_o2: absolute clamped tap offsets (o00, o01, o10, o11)
//   g_a:  rm1/s
__device__ float4 g_w[NHW];
__device__ int4   g_o2[NHW];
__device__ float  g_a[NHW];

// -------------------------------------------------------------------------
// Kernel 1: per coarse pixel param computation.
// Bilinear resize 768x1280 -> 192x320 is exactly the mean of the 2x2 block
// at (4h+1, 4w+1) (fractional weights are exactly 0.5).
// -------------------------------------------------------------------------
__global__ void params_kernel(const float* __restrict__ flow,
                              const float* __restrict__ mask1,
                              const float* __restrict__ mask1n)
{
#if __CUDA_ARCH__ >= 900
    cudaTriggerProgrammaticLaunchCompletion();
#endif
    int idx = blockIdx.x * blockDim.x + threadIdx.x;
    if (idx >= NHW) return;
    int w = idx % WW;
    int h = (idx / WW) % HH;
    int n = idx / HWc;

    size_t o00 = (size_t)(4*h + 1) * FWW + (4*w + 1);

    const float* flx = flow + (size_t)n * 2 * FHW;
    const float* fly = flx + (size_t)FHW;
    float rfx = 0.0625f * (flx[o00] + flx[o00+1] + flx[o00+FWW] + flx[o00+FWW+1]);
    float rfy = 0.0625f * (fly[o00] + fly[o00+1] + fly[o00+FWW] + fly[o00+FWW+1]);

    float px = ((float)w + rfx) * ((float)WW / (float)(WW-1)) - 0.5f;
    float py = ((float)h + rfy) * ((float)HH / (float)(HH-1)) - 0.5f;

    const float* m1 = mask1 + (size_t)n * FHW;
    float rm1 = 0.25f * (m1[o00] + m1[o00+1] + m1[o00+FWW] + m1[o00+FWW+1]);

    int   x0 = (int)floorf(px);
    int   y0 = (int)floorf(py);
    float wx = px - (float)x0;
    float wy = py - (float)y0;

    const float* mn = mask1n + (size_t)n * FHW;
    float v00 = 0.f, v01 = 0.f, v10 = 0.f, v11 = 0.f;
    bool yv0 = (y0 >= 0)   & (y0 < HH);
    bool yv1 = (y0+1 >= 0) & (y0+1 < HH);
    bool xv0 = (x0 >= 0)   & (x0 < WW);
    bool xv1 = (x0+1 >= 0) & (x0+1 < WW);
    if (yv0 & xv0) { size_t o = (size_t)(4*y0+1)*FWW + (4*x0+1);
        v00 = 0.25f*(mn[o]+mn[o+1]+mn[o+FWW]+mn[o+FWW+1]); }
    if (yv0 & xv1) { size_t o = (size_t)(4*y0+1)*FWW + (4*(x0+1)+1);
        v01 = 0.25f*(mn[o]+mn[o+1]+mn[o+FWW]+mn[o+FWW+1]); }
    if (yv1 & xv0) { size_t o = (size_t)(4*(y0+1)+1)*FWW + (4*x0+1);
        v10 = 0.25f*(mn[o]+mn[o+1]+mn[o+FWW]+mn[o+FWW+1]); }
    if (yv1 & xv1) { size_t o = (size_t)(4*(y0+1)+1)*FWW + (4*(x0+1)+1);
        v11 = 0.25f*(mn[o]+mn[o+1]+mn[o+FWW]+mn[o+FWW+1]); }

    float rm1n = v00*(1.f-wx)*(1.f-wy) + v01*wx*(1.f-wy)
               + v10*(1.f-wx)*wy       + v11*wx*wy;

    float s = rm1 + rm1n;
    if (s == 0.0f) s = 1e-6f;
    float a = rm1 / s;
    float b = rm1n / s;

    int x0c = min(max(x0, 0), WW-1);
    int x1c = min(max(x0+1, 0), WW-1);
    int y0c = min(max(y0, 0), HH-1);
    int y1c = min(max(y0+1, 0), HH-1);

    float w00 = (yv0 & xv0) ? b*(1.f-wx)*(1.f-wy) : 0.f;
    float w01 = (yv0 & xv1) ? b*wx*(1.f-wy)       : 0.f;
    float w10 = (yv1 & xv0) ? b*(1.f-wx)*wy       : 0.f;
    float w11 = (yv1 & xv1) ? b*wx*wy             : 0.f;

    g_w[idx]  = make_float4(w00, w01, w10, w11);
    g_o2[idx] = make_int4(y0c*WW + x0c, y0c*WW + x1c,
                          y1c*WW + x0c, y1c*WW + x1c);
    g_a[idx]  = a;
}

// -------------------------------------------------------------------------
// Fuse block body: same pixel, TWO channels per iteration (planes c and
// c+8). Both channel chains share all params and tap offsets — the second
// plane is a constant CSTRIDE element offset on the same pointers (LDG
// immediate offset, zero extra address registers). Doubles in-flight loads
// without a second gather window or extra param traffic.
// -------------------------------------------------------------------------
__device__ __forceinline__ void fuse_block(
        int fidx,
        const float* __restrict__ fmap1,
        const float* __restrict__ fmap1n,
        float* __restrict__ out)
{
    int bx    = fidx % (HWc / 256);       // 0..239 spatial block
    int by    = fidx / (HWc / 256);       // 0..127 (n * CHUNKS + chunk)
    int sp    = bx * 256 + threadIdx.x;
    int n     = by / CHUNKS;
    int cbase = (by % CHUNKS) * CH;

    float4 wv = g_w[n * HWc + sp];
    int4   ov = g_o2[n * HWc + sp];
    float  a  = g_a[n * HWc + sp];

    size_t plane = ((size_t)(n * CC + cbase)) * HWc;
    const float* f1 = fmap1  + plane + sp;
    const float* fn = fmap1n + plane;
    float*       o  = out    + plane + sp;

    #pragma unroll 2
    for (int c = 0; c < HCH; c++) {
        // channel c
        float t00 = fn[ov.x];
        float t01 = fn[ov.y];
        float t10 = fn[ov.z];
        float t11 = fn[ov.w];
        // channel c+8 (independent chain, same offsets + immediate)
        float s00 = fn[CSTRIDE + ov.x];
        float s01 = fn[CSTRIDE + ov.y];
        float s10 = fn[CSTRIDE + ov.z];
        float s11 = fn[CSTRIDE + ov.w];
        float f0  = f1[0];
        float f8  = f1[CSTRIDE];

        float r0 = a * f0
                 + wv.x * t00 + wv.y * t01 + wv.z * t10 + wv.w * t11;
        float r8 = a * f8
                 + wv.x * s00 + wv.y * s01 + wv.z * s10 + wv.w * s11;
        o[0]       = r0;
        o[CSTRIDE] = r8;
        f1 += HWc; fn += HWc; o += HWc;
    }
}

// -------------------------------------------------------------------------
// Upsample block body: convex upsample of coarse flow channel 0, factor 4.
// One thread per (n, yf, w): produces the 4 fx outputs (contiguous float4).
// Independent of params_kernel output.
// -------------------------------------------------------------------------
__device__ __forceinline__ void upsample_block(
        int uidx,
        const float* __restrict__ cflow,
        const float* __restrict__ umask,
        float* __restrict__ out)
{
    int idx = uidx * 256 + threadIdx.x;
    int w  = idx % WW;
    int yf = (idx / WW) % FHH;
    int n  = idx / (WW * FHH);
    int h = yf >> 2, fy = yf & 3;

    const float* fb = cflow + (size_t)n * 2 * HWc;
    float fv[9];
    #pragma unroll
    for (int k = 0; k < 9; k++) {
        int dy = k / 3 - 1, dxk = k % 3 - 1;
        int hh = h + dy, ww = w + dxk;
        fv[k] = ((hh >= 0) & (hh < HH) & (ww >= 0) & (ww < WW))
                  ? fb[hh * WW + ww] : 0.f;
    }

    const float* mb = umask + (size_t)n * 144 * HWc
                            + (size_t)(fy * 4) * HWc
                            + (size_t)h * WW + w;
    float4 res;
    float* resp = (float*)&res;
    #pragma unroll
    for (int fx = 0; fx < 4; fx++) {
        float m[9];
        float mx = -1e30f;
        #pragma unroll
        for (int k = 0; k < 9; k++) {
            m[k] = mb[(size_t)(k * 16 + fx) * HWc];
            mx = fmaxf(mx, m[k]);
        }
        float num = 0.f, den = 0.f;
        #pragma unroll
        for (int k = 0; k < 9; k++) {
            float e = __expf(m[k] - mx);
            den += e;
            num += e * fv[k];
        }
        resp[fx] = 4.0f * num / den;
    }

    float4* op = (float4*)(out + FUSED_ELEMS
                               + (size_t)n * FHW + (size_t)yf * FWW + 4 * w);
    *op = res;
}

// -------------------------------------------------------------------------
// Kernel 2: merged fuse + upsample with PDL. Every 5th block runs upsample
// (independent of params — starts immediately); fuse blocks grid-sync on
// params completion. launch_bounds(256,6): <=42 regs, >=6 blocks/SM.
// -------------------------------------------------------------------------
__global__ void __launch_bounds__(256, 6) merged_kernel(
        const float* __restrict__ fmap1,
        const float* __restrict__ fmap1n,
        const float* __restrict__ cflow,
        const float* __restrict__ umask,
        float* __restrict__ out)
{
    int b = blockIdx.x;
    int q = b / 5;
    int r = b - q * 5;
    if (r == 4) {
        upsample_block(q, cflow, umask, out);
    } else {
#if __CUDA_ARCH__ >= 900
        cudaGridDependencySynchronize();
#endif
        fuse_block(q * 4 + r, fmap1, fmap1n, out);
    }
}

// -------------------------------------------------------------------------
extern "C" void kernel_launch(void* const* d_in, const int* in_sizes, int n_in,
                              void* d_out, int out_size)
{
    const float* fmap1   = (const float*)d_in[0];
    const float* fmap1n  = (const float*)d_in[1];
    const float* flow    = (const float*)d_in[2];
    const float* mask1   = (const float*)d_in[3];
    const float* mask1n  = (const float*)d_in[4];
    const float* cflow   = (const float*)d_in[5];
    const float* umask   = (const float*)d_in[6];

    float* out = (float*)d_out;

    const int T = 256;
    params_kernel<<<(NHW + T - 1) / T, T>>>(flow, mask1, mask1n);

    cudaLaunchConfig_t cfg = {};
    cfg.gridDim  = dim3(ALL_BLOCKS, 1, 1);
    cfg.blockDim = dim3(T, 1, 1);
    cfg.dynamicSmemBytes = 0;
    cfg.stream = 0;
    cudaLaunchAttribute attrs[1];
    attrs[0].id = cudaLaunchAttributeProgrammaticStreamSerialization;
    attrs[0].val.programmaticStreamSerializationAllowed = 1;
    cfg.attrs = attrs;
    cfg.numAttrs = 1;
    cudaLaunchKernelEx(&cfg, merged_kernel, fmap1, fmap1n, cflow, umask, out);
}

// round 16
// speedup vs baseline: 1.0445x; 1.0445x over previous
#include <cuda_runtime.h>
#include <math.h>

#define NB   8
#define CC   256
#define HH   192
#define WW   320
#define FHH  768
#define FWW  1280
#define HWc  (HH*WW)          // 61440 coarse pixels
#define NHW  (NB*HWc)         // 491520
#define FHW  (FHH*FWW)        // 983040 fine pixels
#define FUSED_ELEMS ((size_t)NB*CC*HWc)   // 125,829,120
#define CH   16               // channels per fuse block
#define CHUNKS (CC/CH)        // 16
#define FUSE_BLOCKS  (HWc/256 * NB * CHUNKS)   // 240*128 = 30720
#define UP_BLOCKS    (NB*FHH*WW/256)           // 7680
#define ALL_BLOCKS   (FUSE_BLOCKS + UP_BLOCKS) // 38400 = 5 * 7680

// Precomputed per-(n,h,w):
//   g_w: (b*w00, b*w01, b*w10, b*w11) — bilinear weights * rm1n/s, invalid taps zeroed
//   g_p: packed (o00|o01<<16, o10|o11<<16, float_bits(a), 0)
//        offsets are absolute clamped in-plane indices (< 61440, fit u16)
__device__ float4 g_w[NHW];
__device__ uint4  g_p[NHW];

// -------------------------------------------------------------------------
// Kernel 1: per coarse pixel param computation.
// Bilinear resize 768x1280 -> 192x320 is exactly the mean of the 2x2 block
// at (4h+1, 4w+1) (fractional weights are exactly 0.5).
// -------------------------------------------------------------------------
__global__ void params_kernel(const float* __restrict__ flow,
                              const float* __restrict__ mask1,
                              const float* __restrict__ mask1n)
{
#if __CUDA_ARCH__ >= 900
    cudaTriggerProgrammaticLaunchCompletion();
#endif
    int idx = blockIdx.x * blockDim.x + threadIdx.x;
    if (idx >= NHW) return;
    int w = idx % WW;
    int h = (idx / WW) % HH;
    int n = idx / HWc;

    size_t o00 = (size_t)(4*h + 1) * FWW + (4*w + 1);

    const float* flx = flow + (size_t)n * 2 * FHW;
    const float* fly = flx + (size_t)FHW;
    float rfx = 0.0625f * (flx[o00] + flx[o00+1] + flx[o00+FWW] + flx[o00+FWW+1]);
    float rfy = 0.0625f * (fly[o00] + fly[o00+1] + fly[o00+FWW] + fly[o00+FWW+1]);

    float px = ((float)w + rfx) * ((float)WW / (float)(WW-1)) - 0.5f;
    float py = ((float)h + rfy) * ((float)HH / (float)(HH-1)) - 0.5f;

    const float* m1 = mask1 + (size_t)n * FHW;
    float rm1 = 0.25f * (m1[o00] + m1[o00+1] + m1[o00+FWW] + m1[o00+FWW+1]);

    int   x0 = (int)floorf(px);
    int   y0 = (int)floorf(py);
    float wx = px - (float)x0;
    float wy = py - (float)y0;

    const float* mn = mask1n + (size_t)n * FHW;
    float v00 = 0.f, v01 = 0.f, v10 = 0.f, v11 = 0.f;
    bool yv0 = (y0 >= 0)   & (y0 < HH);
    bool yv1 = (y0+1 >= 0) & (y0+1 < HH);
    bool xv0 = (x0 >= 0)   & (x0 < WW);
    bool xv1 = (x0+1 >= 0) & (x0+1 < WW);
    if (yv0 & xv0) { size_t o = (size_t)(4*y0+1)*FWW + (4*x0+1);
        v00 = 0.25f*(mn[o]+mn[o+1]+mn[o+FWW]+mn[o+FWW+1]); }
    if (yv0 & xv1) { size_t o = (size_t)(4*y0+1)*FWW + (4*(x0+1)+1);
        v01 = 0.25f*(mn[o]+mn[o+1]+mn[o+FWW]+mn[o+FWW+1]); }
    if (yv1 & xv0) { size_t o = (size_t)(4*(y0+1)+1)*FWW + (4*x0+1);
        v10 = 0.25f*(mn[o]+mn[o+1]+mn[o+FWW]+mn[o+FWW+1]); }
    if (yv1 & xv1) { size_t o = (size_t)(4*(y0+1)+1)*FWW + (4*(x0+1)+1);
        v11 = 0.25f*(mn[o]+mn[o+1]+mn[o+FWW]+mn[o+FWW+1]); }

    float rm1n = v00*(1.f-wx)*(1.f-wy) + v01*wx*(1.f-wy)
               + v10*(1.f-wx)*wy       + v11*wx*wy;

    float s = rm1 + rm1n;
    if (s == 0.0f) s = 1e-6f;
    float a = rm1 / s;
    float b = rm1n / s;

    int x0c = min(max(x0, 0), WW-1);
    int x1c = min(max(x0+1, 0), WW-1);
    int y0c = min(max(y0, 0), HH-1);
    int y1c = min(max(y0+1, 0), HH-1);

    float w00 = (yv0 & xv0) ? b*(1.f-wx)*(1.f-wy) : 0.f;
    float w01 = (yv0 & xv1) ? b*wx*(1.f-wy)       : 0.f;
    float w10 = (yv1 & xv0) ? b*(1.f-wx)*wy       : 0.f;
    float w11 = (yv1 & xv1) ? b*wx*wy             : 0.f;

    unsigned u00 = (unsigned)(y0c*WW + x0c);
    unsigned u01 = (unsigned)(y0c*WW + x1c);
    unsigned u10 = (unsigned)(y1c*WW + x0c);
    unsigned u11 = (unsigned)(y1c*WW + x1c);

    g_w[idx] = make_float4(w00, w01, w10, w11);
    g_p[idx] = make_uint4(u00 | (u01 << 16), u10 | (u11 << 16),
                          __float_as_uint(a), 0u);
}

// -------------------------------------------------------------------------
// Fuse block body (R14 structure: 1 px/thread, unroll 4, 32-reg friendly,
// absolute tap offsets, now packed: 2 param loads instead of 3).
// -------------------------------------------------------------------------
__device__ __forceinline__ void fuse_block(
        int fidx,
        const float* __restrict__ fmap1,
        const float* __restrict__ fmap1n,
        float* __restrict__ out)
{
    int bx    = fidx % (HWc / 256);       // 0..239 spatial block
    int by    = fidx / (HWc / 256);       // 0..127 (n * CHUNKS + chunk)
    int sp    = bx * 256 + threadIdx.x;
    int n     = by / CHUNKS;
    int cbase = (by % CHUNKS) * CH;

    float4 wv = g_w[n * HWc + sp];
    uint4  pk = g_p[n * HWc + sp];
    int o00 = (int)(pk.x & 0xFFFFu);
    int o01 = (int)(pk.x >> 16);
    int o10 = (int)(pk.y & 0xFFFFu);
    int o11 = (int)(pk.y >> 16);
    float a = __uint_as_float(pk.z);

    size_t plane = ((size_t)(n * CC + cbase)) * HWc;
    const float* f1 = fmap1  + plane + sp;
    const float* fn = fmap1n + plane;
    float*       o  = out    + plane + sp;

    #pragma unroll 4
    for (int c = 0; c < CH; c++) {
        float t00 = fn[o00];
        float t01 = fn[o01];
        float t10 = fn[o10];
        float t11 = fn[o11];
        float r = a * f1[0]
                + wv.x * t00 + wv.y * t01 + wv.z * t10 + wv.w * t11;
        o[0] = r;
        f1 += HWc; fn += HWc; o += HWc;
    }
}

// -------------------------------------------------------------------------
// Upsample block body: convex upsample of coarse flow channel 0, factor 4.
// One thread per (n, yf, w): produces the 4 fx outputs (contiguous float4).
// Independent of params_kernel output.
// -------------------------------------------------------------------------
__device__ __forceinline__ void upsample_block(
        int uidx,
        const float* __restrict__ cflow,
        const float* __restrict__ umask,
        float* __restrict__ out)
{
    int idx = uidx * 256 + threadIdx.x;
    int w  = idx % WW;
    int yf = (idx / WW) % FHH;
    int n  = idx / (WW * FHH);
    int h = yf >> 2, fy = yf & 3;

    const float* fb = cflow + (size_t)n * 2 * HWc;
    float fv[9];
    #pragma unroll
    for (int k = 0; k < 9; k++) {
        int dy = k / 3 - 1, dxk = k % 3 - 1;
        int hh = h + dy, ww = w + dxk;
        fv[k] = ((hh >= 0) & (hh < HH) & (ww >= 0) & (ww < WW))
                  ? fb[hh * WW + ww] : 0.f;
    }

    const float* mb = umask + (size_t)n * 144 * HWc
                            + (size_t)(fy * 4) * HWc
                            + (size_t)h * WW + w;
    float4 res;
    float* resp = (float*)&res;
    #pragma unroll
    for (int fx = 0; fx < 4; fx++) {
        float m[9];
        float mx = -1e30f;
        #pragma unroll
        for (int k = 0; k < 9; k++) {
            m[k] = mb[(size_t)(k * 16 + fx) * HWc];
            mx = fmaxf(mx, m[k]);
        }
        float num = 0.f, den = 0.f;
        #pragma unroll
        for (int k = 0; k < 9; k++) {
            float e = __expf(m[k] - mx);
            den += e;
            num += e * fv[k];
        }
        resp[fx] = 4.0f * num / den;
    }

    float4* op = (float4*)(out + FUSED_ELEMS
                               + (size_t)n * FHW + (size_t)yf * FWW + 4 * w);
    *op = res;
}

// -------------------------------------------------------------------------
// Kernel 2: merged fuse + upsample with PDL. Every 5th block runs upsample
// (independent of params — starts immediately); fuse blocks grid-sync on
// params completion.
// -------------------------------------------------------------------------
__global__ void __launch_bounds__(256) merged_kernel(
        const float* __restrict__ fmap1,
        const float* __restrict__ fmap1n,
        const float* __restrict__ cflow,
        const float* __restrict__ umask,
        float* __restrict__ out)
{
    int b = blockIdx.x;
    int q = b / 5;
    int r = b - q * 5;
    if (r == 4) {
        upsample_block(q, cflow, umask, out);
    } else {
#if __CUDA_ARCH__ >= 900
        cudaGridDependencySynchronize();
#endif
        fuse_block(q * 4 + r, fmap1, fmap1n, out);
    }
}

// -------------------------------------------------------------------------
extern "C" void kernel_launch(void* const* d_in, const int* in_sizes, int n_in,
                              void* d_out, int out_size)
{
    const float* fmap1   = (const float*)d_in[0];
    const float* fmap1n  = (const float*)d_in[1];
    const float* flow    = (const float*)d_in[2];
    const float* mask1   = (const float*)d_in[3];
    const float* mask1n  = (const float*)d_in[4];
    const float* cflow   = (const float*)d_in[5];
    const float* umask   = (const float*)d_in[6];

    float* out = (float*)d_out;

    const int T = 256;
    params_kernel<<<(NHW + T - 1) / T, T>>>(flow, mask1, mask1n);

    cudaLaunchConfig_t cfg = {};
    cfg.gridDim  = dim3(ALL_BLOCKS, 1, 1);
    cfg.blockDim = dim3(T, 1, 1);
    cfg.dynamicSmemBytes = 0;
    cfg.stream = 0;
    cudaLaunchAttribute attrs[1];
    attrs[0].id = cudaLaunchAttributeProgrammaticStreamSerialization;
    attrs[0].val.programmaticStreamSerializationAllowed = 1;
    cfg.attrs = attrs;
    cfg.numAttrs = 1;
    cudaLaunchKernelEx(&cfg, merged_kernel, fmap1, fmap1n, cflow, umask, out);
}

// round 17
// speedup vs baseline: 1.0535x; 1.0086x over previous
#include <cuda_runtime.h>
#include <math.h>

#define NB   8
#define CC   256
#define HH   192
#define WW   320
#define FHH  768
#define FWW  1280
#define HWc  (HH*WW)          // 61440 coarse pixels
#define NHW  (NB*HWc)         // 491520
#define FHW  (FHH*FWW)        // 983040 fine pixels
#define FUSED_ELEMS ((size_t)NB*CC*HWc)   // 125,829,120
#define CH   16               // channels per fuse block
#define CHUNKS (CC/CH)        // 16
#define FUSE_BLOCKS  (HWc/256 * NB * CHUNKS)   // 240*128 = 30720
#define UP_BLOCKS    (NB*FHH*WW/256)           // 7680
#define ALL_BLOCKS   (FUSE_BLOCKS + UP_BLOCKS) // 38400
#define UP_FRONT     2560                      // upsample slab at grid start
// remainder: 35840 blocks = 5120 groups of 7 (6 fuse + 1 upsample)

// Precomputed per-(n,h,w):
//   g_w:  (b*w00, b*w01, b*w10, b*w11) — bilinear weights * rm1n/s, invalid taps zeroed
//   g_o2: absolute clamped tap offsets (o00, o01, o10, o11)
//   g_a:  rm1/s
__device__ float4 g_w[NHW];
__device__ int4   g_o2[NHW];
__device__ float  g_a[NHW];

// -------------------------------------------------------------------------
// Kernel 1: per coarse pixel param computation.
// Bilinear resize 768x1280 -> 192x320 is exactly the mean of the 2x2 block
// at (4h+1, 4w+1) (fractional weights are exactly 0.5).
// -------------------------------------------------------------------------
__global__ void params_kernel(const float* __restrict__ flow,
                              const float* __restrict__ mask1,
                              const float* __restrict__ mask1n)
{
#if __CUDA_ARCH__ >= 900
    cudaTriggerProgrammaticLaunchCompletion();
#endif
    int idx = blockIdx.x * blockDim.x + threadIdx.x;
    if (idx >= NHW) return;
    int w = idx % WW;
    int h = (idx / WW) % HH;
    int n = idx / HWc;

    size_t o00 = (size_t)(4*h + 1) * FWW + (4*w + 1);

    const float* flx = flow + (size_t)n * 2 * FHW;
    const float* fly = flx + (size_t)FHW;
    float rfx = 0.0625f * (flx[o00] + flx[o00+1] + flx[o00+FWW] + flx[o00+FWW+1]);
    float rfy = 0.0625f * (fly[o00] + fly[o00+1] + fly[o00+FWW] + fly[o00+FWW+1]);

    float px = ((float)w + rfx) * ((float)WW / (float)(WW-1)) - 0.5f;
    float py = ((float)h + rfy) * ((float)HH / (float)(HH-1)) - 0.5f;

    const float* m1 = mask1 + (size_t)n * FHW;
    float rm1 = 0.25f * (m1[o00] + m1[o00+1] + m1[o00+FWW] + m1[o00+FWW+1]);

    int   x0 = (int)floorf(px);
    int   y0 = (int)floorf(py);
    float wx = px - (float)x0;
    float wy = py - (float)y0;

    const float* mn = mask1n + (size_t)n * FHW;
    float v00 = 0.f, v01 = 0.f, v10 = 0.f, v11 = 0.f;
    bool yv0 = (y0 >= 0)   & (y0 < HH);
    bool yv1 = (y0+1 >= 0) & (y0+1 < HH);
    bool xv0 = (x0 >= 0)   & (x0 < WW);
    bool xv1 = (x0+1 >= 0) & (x0+1 < WW);
    if (yv0 & xv0) { size_t o = (size_t)(4*y0+1)*FWW + (4*x0+1);
        v00 = 0.25f*(mn[o]+mn[o+1]+mn[o+FWW]+mn[o+FWW+1]); }
    if (yv0 & xv1) { size_t o = (size_t)(4*y0+1)*FWW + (4*(x0+1)+1);
        v01 = 0.25f*(mn[o]+mn[o+1]+mn[o+FWW]+mn[o+FWW+1]); }
    if (yv1 & xv0) { size_t o = (size_t)(4*(y0+1)+1)*FWW + (4*x0+1);
        v10 = 0.25f*(mn[o]+mn[o+1]+mn[o+FWW]+mn[o+FWW+1]); }
    if (yv1 & xv1) { size_t o = (size_t)(4*(y0+1)+1)*FWW + (4*(x0+1)+1);
        v11 = 0.25f*(mn[o]+mn[o+1]+mn[o+FWW]+mn[o+FWW+1]); }

    float rm1n = v00*(1.f-wx)*(1.f-wy) + v01*wx*(1.f-wy)
               + v10*(1.f-wx)*wy       + v11*wx*wy;

    float s = rm1 + rm1n;
    if (s == 0.0f) s = 1e-6f;
    float a = rm1 / s;
    float b = rm1n / s;

    int x0c = min(max(x0, 0), WW-1);
    int x1c = min(max(x0+1, 0), WW-1);
    int y0c = min(max(y0, 0), HH-1);
    int y1c = min(max(y0+1, 0), HH-1);

    float w00 = (yv0 & xv0) ? b*(1.f-wx)*(1.f-wy) : 0.f;
    float w01 = (yv0 & xv1) ? b*wx*(1.f-wy)       : 0.f;
    float w10 = (yv1 & xv0) ? b*(1.f-wx)*wy       : 0.f;
    float w11 = (yv1 & xv1) ? b*wx*wy             : 0.f;

    g_w[idx]  = make_float4(w00, w01, w10, w11);
    g_o2[idx] = make_int4(y0c*WW + x0c, y0c*WW + x1c,
                          y1c*WW + x0c, y1c*WW + x1c);
    g_a[idx]  = a;
}

// -------------------------------------------------------------------------
// Fuse block body (R14 exact: 1 px/thread, unroll 4, 32 regs, absolute
// tap offsets, 3 param loads).
// -------------------------------------------------------------------------
__device__ __forceinline__ void fuse_block(
        int fidx,
        const float* __restrict__ fmap1,
        const float* __restrict__ fmap1n,
        float* __restrict__ out)
{
    int bx    = fidx % (HWc / 256);       // 0..239 spatial block
    int by    = fidx / (HWc / 256);       // 0..127 (n * CHUNKS + chunk)
    int sp    = bx * 256 + threadIdx.x;
    int n     = by / CHUNKS;
    int cbase = (by % CHUNKS) * CH;

    float4 wv = g_w[n * HWc + sp];
    int4   ov = g_o2[n * HWc + sp];
    float  a  = g_a[n * HWc + sp];

    size_t plane = ((size_t)(n * CC + cbase)) * HWc;
    const float* f1 = fmap1  + plane + sp;
    const float* fn = fmap1n + plane;
    float*       o  = out    + plane + sp;

    #pragma unroll 4
    for (int c = 0; c < CH; c++) {
        float t00 = fn[ov.x];
        float t01 = fn[ov.y];
        float t10 = fn[ov.z];
        float t11 = fn[ov.w];
        float r = a * f1[0]
                + wv.x * t00 + wv.y * t01 + wv.z * t10 + wv.w * t11;
        o[0] = r;
        f1 += HWc; fn += HWc; o += HWc;
    }
}

// -------------------------------------------------------------------------
// Upsample block body: convex upsample of coarse flow channel 0, factor 4.
// One thread per (n, yf, w): produces the 4 fx outputs (contiguous float4).
// Independent of params_kernel output.
// -------------------------------------------------------------------------
__device__ __forceinline__ void upsample_block(
        int uidx,
        const float* __restrict__ cflow,
        const float* __restrict__ umask,
        float* __restrict__ out)
{
    int idx = uidx * 256 + threadIdx.x;
    int w  = idx % WW;
    int yf = (idx / WW) % FHH;
    int n  = idx / (WW * FHH);
    int h = yf >> 2, fy = yf & 3;

    const float* fb = cflow + (size_t)n * 2 * HWc;
    float fv[9];
    #pragma unroll
    for (int k = 0; k < 9; k++) {
        int dy = k / 3 - 1, dxk = k % 3 - 1;
        int hh = h + dy, ww = w + dxk;
        fv[k] = ((hh >= 0) & (hh < HH) & (ww >= 0) & (ww < WW))
                  ? fb[hh * WW + ww] : 0.f;
    }

    const float* mb = umask + (size_t)n * 144 * HWc
                            + (size_t)(fy * 4) * HWc
                            + (size_t)h * WW + w;
    float4 res;
    float* resp = (float*)&res;
    #pragma unroll
    for (int fx = 0; fx < 4; fx++) {
        float m[9];
        float mx = -1e30f;
        #pragma unroll
        for (int k = 0; k < 9; k++) {
            m[k] = mb[(size_t)(k * 16 + fx) * HWc];
            mx = fmaxf(mx, m[k]);
        }
        float num = 0.f, den = 0.f;
        #pragma unroll
        for (int k = 0; k < 9; k++) {
            float e = __expf(m[k] - mx);
            den += e;
            num += e * fv[k];
        }
        resp[fx] = 4.0f * num / den;
    }

    float4* op = (float4*)(out + FUSED_ELEMS
                               + (size_t)n * FHW + (size_t)yf * FWW + 4 * w);
    *op = res;
}

// -------------------------------------------------------------------------
// Kernel 2: merged fuse + upsample with PDL + front-loaded upsample slab.
// Blocks [0, UP_FRONT): pure upsample — no params dependency, so under PDL
// they fill the machine while params_kernel is still running. Remaining
// 35840 blocks: groups of 7 = 6 fuse (grid-sync on params) + 1 upsample,
// preserving the streaming/gather mix through the bulk and tail.
// -------------------------------------------------------------------------
__global__ void __launch_bounds__(256) merged_kernel(
        const float* __restrict__ fmap1,
        const float* __restrict__ fmap1n,
        const float* __restrict__ cflow,
        const float* __restrict__ umask,
        float* __restrict__ out)
{
    int b = blockIdx.x;
    if (b < UP_FRONT) {
        upsample_block(b, cflow, umask, out);
        return;
    }
    int bb = b - UP_FRONT;
    int q = bb / 7;
    int r = bb - q * 7;
    if (r == 6) {
        upsample_block(UP_FRONT + q, cflow, umask, out);
    } else {
#if __CUDA_ARCH__ >= 900
        cudaGridDependencySynchronize();
#endif
        fuse_block(q * 6 + r, fmap1, fmap1n, out);
    }
}

// -------------------------------------------------------------------------
extern "C" void kernel_launch(void* const* d_in, const int* in_sizes, int n_in,
                              void* d_out, int out_size)
{
    const float* fmap1   = (const float*)d_in[0];
    const float* fmap1n  = (const float*)d_in[1];
    const float* flow    = (const float*)d_in[2];
    const float* mask1   = (const float*)d_in[3];
    const float* mask1n  = (const float*)d_in[4];
    const float* cflow   = (const float*)d_in[5];
    const float* umask   = (const float*)d_in[6];

    float* out = (float*)d_out;

    const int T = 256;
    params_kernel<<<(NHW + T - 1) / T, T>>>(flow, mask1, mask1n);

    cudaLaunchConfig_t cfg = {};
    cfg.gridDim  = dim3(ALL_BLOCKS, 1, 1);
    cfg.blockDim = dim3(T, 1, 1);
    cfg.dynamicSmemBytes = 0;
    cfg.stream = 0;
    cudaLaunchAttribute attrs[1];
    attrs[0].id = cudaLaunchAttributeProgrammaticStreamSerialization;
    attrs[0].val.programmaticStreamSerializationAllowed = 1;
    cfg.attrs = attrs;
    cfg.numAttrs = 1;
    cudaLaunchKernelEx(&cfg, merged_kernel, fmap1, fmap1n, cflow, umask, out);
}